// round 16
// baseline (speedup 1.0000x reference)
#include <cuda_runtime.h>
#include <cuda_bf16.h>
#include <cuda_fp16.h>
#include <math.h>
#include <stdint.h>

#define Bq   128
#define Sq   512
#define Dq   768
#define NHq  8
#define HDq  96
#define HIDq 384
#define Cq   768            // NH*HD
#define Mq   (Bq*Sq)        // 65536 tokens

// ---------------------------------------------------------------------------
// Scratch (__device__ globals; cudaMalloc is forbidden)
// ---------------------------------------------------------------------------
__device__ __half  g_Ph [(size_t)Cq * Dq];   // P fp16
__device__ __half  g_W1b[(size_t)NHq * HIDq * HDq];
__device__ __half  g_W2b[(size_t)NHq * HDq * HIDq];
__device__ float   g_part[(size_t)(Mq/128) * 3 * Cq];  // [mtile][{m,l,a}][768]

// ---------------------------------------------------------------------------
// Generic-PTX tensor-core helpers (plain sm_103 target safe)
// ---------------------------------------------------------------------------
__device__ __forceinline__ uint32_t smem_u32(const void* p) {
    uint32_t a;
    asm("{ .reg .u64 t; cvta.to.shared.u64 t, %1; cvt.u32.u64 %0, t; }"
        : "=r"(a) : "l"(p));
    return a;
}
__device__ __forceinline__ void mma16816(float* c, const uint32_t* a, const uint32_t* b) {
    asm volatile("mma.sync.aligned.m16n8k16.row.col.f32.f16.f16.f32 "
        "{%0,%1,%2,%3}, {%4,%5,%6,%7}, {%8,%9}, {%0,%1,%2,%3};"
        : "+f"(c[0]), "+f"(c[1]), "+f"(c[2]), "+f"(c[3])
        : "r"(a[0]), "r"(a[1]), "r"(a[2]), "r"(a[3]), "r"(b[0]), "r"(b[1]));
}
__device__ __forceinline__ void ldsm_x4(uint32_t* r, uint32_t addr) {
    asm volatile("ldmatrix.sync.aligned.m8n8.x4.shared.b16 {%0,%1,%2,%3}, [%4];"
        : "=r"(r[0]), "=r"(r[1]), "=r"(r[2]), "=r"(r[3]) : "r"(addr));
}
__device__ __forceinline__ void cp16(uint32_t dst, const void* src) {
    asm volatile("cp.async.cg.shared.global [%0], [%1], 16;" :: "r"(dst), "l"(src));
}
#define CP_COMMIT()  asm volatile("cp.async.commit_group;" ::: "memory")
#define CP_WAIT(n)   asm volatile("cp.async.wait_group %0;" :: "n"(n) : "memory")
#define SW(o)        ((o) ^ (((o) >> 3) & 0x70))

__device__ __forceinline__ float fexp(float x) {
    x = fmaxf(x, -80.f);
    float t  = x * 1.4426950408889634f;
    float fi = floorf(t);
    float f  = t - fi;
    float p  = 1.8775767e-3f;
    p = fmaf(p, f, 8.9893397e-3f);
    p = fmaf(p, f, 5.5826318e-2f);
    p = fmaf(p, f, 2.4015361e-1f);
    p = fmaf(p, f, 6.9315308e-1f);
    p = fmaf(p, f, 1.0f);
    return __int_as_float(__float_as_int(p) + (((int)fi) << 23));
}

// ---------------------------------------------------------------------------
// K0: P + W1 + W2 fp32 -> fp16 convert in one launch (X handled inside KF)
// ---------------------------------------------------------------------------
#define N4P (Cq * Dq / 4)
#define N4W (NHq * HIDq * HDq / 4)

__global__ __launch_bounds__(256) void k0_misc(
    const float* __restrict__ P, const float* __restrict__ W1,
    const float* __restrict__ W2)
{
    int i = blockIdx.x * 256 + threadIdx.x;
    const float* src;
    __half* dst;
    if (i < N4P)            { src = P;  dst = g_Ph; }
    else {
        i -= N4P;
        if (i < N4W)        { src = W1; dst = g_W1b; }
        else                { i -= N4W; if (i >= N4W) return; src = W2; dst = g_W2b; }
    }
    float4 v = reinterpret_cast<const float4*>(src)[i];
    ushort4 H;
    H.x = __half_as_ushort(__float2half_rn(v.x));
    H.y = __half_as_ushort(__float2half_rn(v.y));
    H.z = __half_as_ushort(__float2half_rn(v.z));
    H.w = __half_as_ushort(__float2half_rn(v.w));
    reinterpret_cast<ushort4*>(dst)[i] = H;
}

// ---------------------------------------------------------------------------
// KF: fused per-(head, 128-token tile) kernel — 96 KB smem, 2 CTAs/SM.
//   Phase A: X read as FP32 via per-warp LDG pipeline, converted to fp16 in
//            registers, stored swizzled to smem (warp-local rows; ordering by
//            the existing per-chunk CTA syncs). P via cp.async, 2 stages.
//   Phase B/C: identical to R15.
// smem OB region (66560): Phase A: Xs 2x16384 @OB | Ps 2x12288 @OB+32768
//                         Phase B: F@OB, W1c@+26624, W2c@+46592
//                         Phase C: Lg fp32 [128][97] @OB
// ---------------------------------------------------------------------------
#define OHH   0
#define OMK   26624
#define ORD   27136
#define OB    29440
#define OXS   OB
#define OPS   (OB + 32768)
#define OF    OB
#define OW1   (OB + 26624)
#define OW2   (OB + 46592)
#define KF_SMEM 96000
#define SHI   208

__global__ __launch_bounds__(256, 2) void kf_fused(
    const float* __restrict__ Xf, const __half* __restrict__ Ph,
    const float* __restrict__ bP,
    const float* __restrict__ b1, const float* __restrict__ b2,
    const float* __restrict__ mask)
{
    extern __shared__ char smem[];
    const uint32_t sb = smem_u32(smem);
    const int tid = threadIdx.x, wid = tid >> 5, lane = tid & 31;
    const int head  = blockIdx.x;
    const int mt    = blockIdx.y;
    const int mtile = mt * 128;
    const int batch = mt >> 2;
    const int soff  = (mt & 3) * 128;
    const int wm  = (wid >> 1) * 32;
    const int wnA = (wid & 1) * 48;

    // ---- prefix-mask early exit (CTA-uniform branch) ----
    if (mask[batch * Sq + soff] < 0.5f) {
        if (tid < 96) {
            float* dst = &g_part[(size_t)mt * 3 * Cq + head * HDq + tid];
            dst[0]      = -1e30f;
            dst[Cq]     = 0.f;
            dst[2 * Cq] = 0.f;
        }
        return;
    }

    const __half* W1h = g_W1b + (size_t)head * HIDq * HDq;
    const __half* W2h = g_W2b + (size_t)head * HDq * HIDq;
    const float* b1h = b1 + head * HIDq;
    const float* b2h = b2 + head * HDq;

    // ======================= Phase A: projection GEMM ======================
    // X: per-warp LDG->cvt->STS pipeline. Each warp owns 16 rows:
    //   lrow = (wid>>1)*32 + (wid&1)*16 + (lane>>1), cols (lane&1)*32..+32.
    const int lrow  = (wid >> 1) * 32 + (wid & 1) * 16 + (lane >> 1);
    const int xcol0 = (lane & 1) * 32;
    const float* xg = Xf + (size_t)(mtile + lrow) * Dq + xcol0;

    float xr[32];
    auto ldg_x = [&](int c) {
        const float4* p = reinterpret_cast<const float4*>(xg + c * 64);
        #pragma unroll
        for (int i = 0; i < 8; i++) {
            float4 v = __ldg(p + i);
            xr[i*4+0] = v.x; xr[i*4+1] = v.y; xr[i*4+2] = v.z; xr[i*4+3] = v.w;
        }
    };
    auto cvt_sts_x = [&](int s) {
        #pragma unroll
        for (int j = 0; j < 4; j++) {
            __half2 h0 = __floats2half2_rn(xr[j*8+0], xr[j*8+1]);
            __half2 h1 = __floats2half2_rn(xr[j*8+2], xr[j*8+3]);
            __half2 h2 = __floats2half2_rn(xr[j*8+4], xr[j*8+5]);
            __half2 h3 = __floats2half2_rn(xr[j*8+6], xr[j*8+7]);
            uint4 v = make_uint4(*reinterpret_cast<uint32_t*>(&h0),
                                 *reinterpret_cast<uint32_t*>(&h1),
                                 *reinterpret_cast<uint32_t*>(&h2),
                                 *reinterpret_cast<uint32_t*>(&h3));
            uint32_t off = SW(lrow * 128 + (lane & 1) * 64 + j * 16);
            *reinterpret_cast<uint4*>(smem + OXS + s * 16384 + off) = v;
        }
    };
    auto load_p = [&](int c, int s) {
        const int kb = c * 64;
        const uint32_t st = sb + OPS + s * 12288;
        #pragma unroll
        for (int t = 0; t < 3; t++) {              // P: 96 rows x 8 col16
            int idx = tid + t * 256;
            int row = idx >> 3, c16 = idx & 7;
            uint32_t off = SW(row * 128 + c16 * 16);
            cp16(st + off, Ph + (size_t)(head * HDq + row) * Dq + kb + c16 * 8);
        }
        CP_COMMIT();
    };

    float accA[2][6][4];
    #pragma unroll
    for (int a = 0; a < 2; a++)
        #pragma unroll
        for (int b = 0; b < 6; b++)
            #pragma unroll
            for (int c = 0; c < 4; c++) accA[a][b][c] = 0.f;

    // prologue: X(0) converted into Xs[0]; X(1) in regs; P(0) in flight
    ldg_x(0);
    load_p(0, 0);
    cvt_sts_x(0);
    ldg_x(1);

    #pragma unroll 1
    for (int c = 0; c < 12; c++) {
        if (c + 1 < 12) { load_p(c + 1, (c + 1) & 1); CP_WAIT(1); }
        else            { CP_WAIT(0); }
        __syncthreads();   // P(c) + Xs[c&1] visible; Xs/Ps[(c+1)&1] free

        if (c + 1 < 12) cvt_sts_x((c + 1) & 1);    // regs hold X(c+1)
        if (c + 2 < 12) ldg_x(c + 2);              // prefetch next

        const uint32_t sXh = sb + OXS + (c & 1) * 16384;
        const uint32_t sPh = sb + OPS + (c & 1) * 12288;
        #pragma unroll
        for (int ks = 0; ks < 4; ks++) {
            uint32_t ah[2][4], bh[3][4];
            #pragma unroll
            for (int mf = 0; mf < 2; mf++) {
                int row = wm + mf * 16 + (lane & 15);
                ldsm_x4(ah[mf], sXh + SW(row * 128 + ((lane >> 4) + ks * 2) * 16));
            }
            #pragma unroll
            for (int p = 0; p < 3; p++) {
                int g = lane >> 3;
                int row = wnA + p * 16 + (g >> 1) * 8 + (lane & 7);
                ldsm_x4(bh[p], sPh + SW(row * 128 + (ks * 2 + (g & 1)) * 16));
            }
            #pragma unroll
            for (int mf = 0; mf < 2; mf++)
                #pragma unroll
                for (int nf = 0; nf < 6; nf++)
                    mma16816(accA[mf][nf], ah[mf], &bh[nf >> 1][(nf & 1) * 2]);
        }
        __syncthreads();      // reads done before stage overwrite
    }

    // Phase A epilogue: accA + bias -> Hi fp16 (OHH); stage mask
    float* mk = reinterpret_cast<float*>(smem + OMK);
    #pragma unroll
    for (int mf = 0; mf < 2; mf++) {
        const int m0 = wm + mf * 16 + (lane >> 2);
        #pragma unroll
        for (int nf = 0; nf < 6; nf++) {
            const int n = wnA + nf * 8 + 2 * (lane & 3);
            const float c0 = __ldg(&bP[head * HDq + n]);
            const float c1 = __ldg(&bP[head * HDq + n + 1]);
            __half2 p0 = __floats2half2_rn(accA[mf][nf][0] + c0, accA[mf][nf][1] + c1);
            __half2 p1 = __floats2half2_rn(accA[mf][nf][2] + c0, accA[mf][nf][3] + c1);
            *reinterpret_cast<uint32_t*>(smem + OHH + m0 * SHI + n * 2) =
                *reinterpret_cast<uint32_t*>(&p0);
            *reinterpret_cast<uint32_t*>(smem + OHH + (m0 + 8) * SHI + n * 2) =
                *reinterpret_cast<uint32_t*>(&p1);
        }
    }
    if (tid < 128) mk[tid] = mask[batch * Sq + soff + tid];

    // ========== Phase B: MLP, 4 hidden chunks of 96, single W buffer =======
    auto load_w = [&](int jc) {
        const int j0 = jc * 96;
        #pragma unroll
        for (int t = 0; t < 5; t++) {              // W1c: 96 x 96 = 1152 cells
            int idx = tid + t * 256;
            if (idx < 1152) {
                int row = idx / 12, c16 = idx % 12;
                cp16(sb + OW1 + row * SHI + c16 * 16,
                     W1h + (size_t)(j0 + row) * HDq + c16 * 8);
            }
        }
        #pragma unroll
        for (int t = 0; t < 5; t++) {              // W2c: 96 x 96 = 1152 cells
            int idx = tid + t * 256;
            if (idx < 1152) {
                int row = idx / 12, c16 = idx % 12;
                cp16(sb + OW2 + row * SHI + c16 * 16,
                     W2h + (size_t)row * HIDq + j0 + c16 * 8);
            }
        }
        CP_COMMIT();
    };

    float acc2[2][6][4];
    #pragma unroll
    for (int a = 0; a < 2; a++)
        #pragma unroll
        for (int b = 0; b < 6; b++)
            #pragma unroll
            for (int c = 0; c < 4; c++) acc2[a][b][c] = 0.f;

    #pragma unroll 1
    for (int jc = 0; jc < 4; jc++) {
        const int j0 = jc * 96;
        __syncthreads();            // prev chunk's W/F reads done; OHH visible (jc=0)
        load_w(jc);
        CP_WAIT(0);
        __syncthreads();            // W chunk visible

        float acc1[2][6][4];
        #pragma unroll
        for (int a = 0; a < 2; a++)
            #pragma unroll
            for (int b = 0; b < 6; b++)
                #pragma unroll
                for (int c = 0; c < 4; c++) acc1[a][b][c] = 0.f;

        // ---- layer 1: F = relu(Hi @ W1c^T + b1), K=96, N=96 ----
        #pragma unroll
        for (int ks = 0; ks < 6; ks++) {
            uint32_t afr[2][4], bfr[3][4];
            #pragma unroll
            for (int mf = 0; mf < 2; mf++) {
                int row = wm + mf * 16 + (lane & 15);
                ldsm_x4(afr[mf], sb + OHH + row * SHI + (lane >> 4) * 16 + ks * 32);
            }
            #pragma unroll
            for (int p = 0; p < 3; p++) {
                int g = lane >> 3;
                int row = wnA + p * 16 + (g >> 1) * 8 + (lane & 7);
                ldsm_x4(bfr[p], sb + OW1 + row * SHI + (g & 1) * 16 + ks * 32);
            }
            #pragma unroll
            for (int mf = 0; mf < 2; mf++)
                #pragma unroll
                for (int nf = 0; nf < 6; nf++)
                    mma16816(acc1[mf][nf], afr[mf], &bfr[nf >> 1][(nf & 1) * 2]);
        }

        // relu + b1 -> F (fp16)
        #pragma unroll
        for (int mf = 0; mf < 2; mf++) {
            const int m0 = wm + mf * 16 + (lane >> 2);
            #pragma unroll
            for (int nf = 0; nf < 6; nf++) {
                const int jl = wnA + nf * 8 + 2 * (lane & 3);
                const float c0 = __ldg(&b1h[j0 + jl]), c1 = __ldg(&b1h[j0 + jl + 1]);
                __half2 p0 = __floats2half2_rn(fmaxf(acc1[mf][nf][0] + c0, 0.f),
                                               fmaxf(acc1[mf][nf][1] + c1, 0.f));
                __half2 p1 = __floats2half2_rn(fmaxf(acc1[mf][nf][2] + c0, 0.f),
                                               fmaxf(acc1[mf][nf][3] + c1, 0.f));
                *reinterpret_cast<uint32_t*>(smem + OF + m0 * SHI + jl * 2) =
                    *reinterpret_cast<uint32_t*>(&p0);
                *reinterpret_cast<uint32_t*>(smem + OF + (m0 + 8) * SHI + jl * 2) =
                    *reinterpret_cast<uint32_t*>(&p1);
            }
        }
        __syncthreads();            // F visible

        // ---- layer 2 partial: acc2 += F @ W2c^T, K=96, N=96 ----
        #pragma unroll
        for (int ks = 0; ks < 6; ks++) {
            uint32_t afr[2][4], bfr[3][4];
            #pragma unroll
            for (int mf = 0; mf < 2; mf++) {
                int row = wm + mf * 16 + (lane & 15);
                ldsm_x4(afr[mf], sb + OF + row * SHI + (lane >> 4) * 16 + ks * 32);
            }
            #pragma unroll
            for (int p = 0; p < 3; p++) {
                int g = lane >> 3;
                int row = wnA + p * 16 + (g >> 1) * 8 + (lane & 7);
                ldsm_x4(bfr[p], sb + OW2 + row * SHI + (g & 1) * 16 + ks * 32);
            }
            #pragma unroll
            for (int mf = 0; mf < 2; mf++)
                #pragma unroll
                for (int nf = 0; nf < 6; nf++)
                    mma16816(acc2[mf][nf], afr[mf], &bfr[nf >> 1][(nf & 1) * 2]);
        }
    }

    // ===================== Phase C: softmax-pool partials ==================
    __syncthreads();                // last L2 MMAs done; OB region reusable
    float* Lg = reinterpret_cast<float*>(smem + OB);    // logits [128][97]
    #pragma unroll
    for (int mf = 0; mf < 2; mf++) {
        const int m0 = wm + mf * 16 + (lane >> 2);
        #pragma unroll
        for (int nf = 0; nf < 6; nf++) {
            const int n = wnA + nf * 8 + 2 * (lane & 3);
            const float c0 = __ldg(&b2h[n]), c1 = __ldg(&b2h[n + 1]);
            Lg[m0 * 97 + n]           = acc2[mf][nf][0] + c0;
            Lg[m0 * 97 + n + 1]       = acc2[mf][nf][1] + c1;
            Lg[(m0 + 8) * 97 + n]     = acc2[mf][nf][2] + c0;
            Lg[(m0 + 8) * 97 + n + 1] = acc2[mf][nf][3] + c1;
        }
    }
    __syncthreads();

    float* red = reinterpret_cast<float*>(smem + ORD);
    if (tid < 192) {
        const int ch = tid % 96, half = tid / 96;
        float m = -1e30f, l = 0.f, a = 0.f;
        for (int t = half * 64; t < half * 64 + 64; t++) {
            if (mk[t] > 0.5f) {
                float x  = Lg[t * 97 + ch];
                float hv = __half2float(*reinterpret_cast<const __half*>(
                               smem + OHH + t * SHI + ch * 2));
                float n  = fmaxf(m, x);
                float sc = fexp(m - n), w = fexp(x - n);
                l = fmaf(l, sc, w);
                a = fmaf(a, sc, w * hv);
                m = n;
            }
        }
        red[(half * 3 + 0) * 96 + ch] = m;
        red[(half * 3 + 1) * 96 + ch] = l;
        red[(half * 3 + 2) * 96 + ch] = a;
    }
    __syncthreads();
    if (tid < 96) {
        const int ch = tid;
        float m0 = red[0 * 96 + ch], l0 = red[1 * 96 + ch], a0 = red[2 * 96 + ch];
        float m1 = red[3 * 96 + ch], l1 = red[4 * 96 + ch], a1 = red[5 * 96 + ch];
        float n  = fmaxf(fmaxf(m0, m1), -1e30f);
        float s0 = fexp(m0 - n), s1 = fexp(m1 - n);
        float* dst = &g_part[(size_t)mt * 3 * Cq + head * HDq + ch];
        dst[0]      = n;
        dst[Cq]     = l0 * s0 + l1 * s1;
        dst[2 * Cq] = a0 * s0 + a1 * s1;
    }
}

// ---------------------------------------------------------------------------
// K3: merge 4 chunk partials per (batch, channel) -> output
// ---------------------------------------------------------------------------
__global__ __launch_bounds__(256) void k3_reduce(float* __restrict__ out)
{
    const int idx = blockIdx.x * 256 + threadIdx.x;
    const int b = idx / Cq, ch = idx % Cq;

    float m = -1e30f;
    #pragma unroll
    for (int c = 0; c < 4; c++)
        m = fmaxf(m, g_part[(size_t)(b * 4 + c) * 3 * Cq + ch]);

    float l = 0.f, a = 0.f;
    #pragma unroll
    for (int c = 0; c < 4; c++) {
        const float* p = &g_part[(size_t)(b * 4 + c) * 3 * Cq + ch];
        float s = fexp(p[0] - m);
        l = fmaf(p[Cq],     s, l);
        a = fmaf(p[2 * Cq], s, a);
    }
    out[idx] = a / l;
}

// ---------------------------------------------------------------------------
extern "C" void kernel_launch(void* const* d_in, const int* in_sizes, int n_in,
                              void* d_out, int out_size)
{
    const float* X    = (const float*)d_in[0];
    const float* mask = (const float*)d_in[1];
    const float* P    = (const float*)d_in[2];
    const float* bP   = (const float*)d_in[3];
    const float* W1   = (const float*)d_in[4];
    const float* b1   = (const float*)d_in[5];
    const float* W2   = (const float*)d_in[6];
    const float* b2   = (const float*)d_in[7];
    float* out = (float*)d_out;

    cudaFuncSetAttribute(kf_fused, cudaFuncAttributeMaxDynamicSharedMemorySize, KF_SMEM);

    __half* Ph;
    cudaGetSymbolAddress((void**)&Ph, g_Ph);

    // K0: P + W converts in one launch (X converted inside KF)
    {
        int ncells = N4P + 2 * N4W;
        k0_misc<<<(ncells + 255) / 256, 256>>>(P, W1, W2);
    }

    // KF: fused projection (in-register X cvt) + MLP + partial softmax-pool
    dim3 gf(NHq, Mq / 128);
    kf_fused<<<gf, 256, KF_SMEM>>>(X, Ph, bP, b1, b2, mask);

    // K3: merge partials
    k3_reduce<<<(Bq * Cq) / 256, 256>>>(out);
}

// round 17
// speedup vs baseline: 1.4410x; 1.4410x over previous
#include <cuda_runtime.h>
#include <cuda_bf16.h>
#include <cuda_fp16.h>
#include <math.h>
#include <stdint.h>

#define Bq   128
#define Sq   512
#define Dq   768
#define NHq  8
#define HDq  96
#define HIDq 384
#define Cq   768            // NH*HD
#define Mq   (Bq*Sq)        // 65536 tokens

// ---------------------------------------------------------------------------
// Scratch (__device__ globals; cudaMalloc is forbidden)
// ---------------------------------------------------------------------------
__device__ __half  g_Xh [(size_t)Mq * Dq];   // 96 MB X fp16
__device__ __half  g_Ph [(size_t)Cq * Dq];   // P fp16
__device__ __half  g_W1b[(size_t)NHq * HIDq * HDq];
__device__ __half  g_W2b[(size_t)NHq * HDq * HIDq];
__device__ float   g_part[(size_t)(Mq/128) * 3 * Cq];  // [mtile][{m,l,a}][768]

// ---------------------------------------------------------------------------
// Generic-PTX tensor-core helpers (plain sm_103 target safe)
// ---------------------------------------------------------------------------
__device__ __forceinline__ uint32_t smem_u32(const void* p) {
    uint32_t a;
    asm("{ .reg .u64 t; cvta.to.shared.u64 t, %1; cvt.u32.u64 %0, t; }"
        : "=r"(a) : "l"(p));
    return a;
}
__device__ __forceinline__ void mma16816(float* c, const uint32_t* a, const uint32_t* b) {
    asm volatile("mma.sync.aligned.m16n8k16.row.col.f32.f16.f16.f32 "
        "{%0,%1,%2,%3}, {%4,%5,%6,%7}, {%8,%9}, {%0,%1,%2,%3};"
        : "+f"(c[0]), "+f"(c[1]), "+f"(c[2]), "+f"(c[3])
        : "r"(a[0]), "r"(a[1]), "r"(a[2]), "r"(a[3]), "r"(b[0]), "r"(b[1]));
}
__device__ __forceinline__ void ldsm_x4(uint32_t* r, uint32_t addr) {
    asm volatile("ldmatrix.sync.aligned.m8n8.x4.shared.b16 {%0,%1,%2,%3}, [%4];"
        : "=r"(r[0]), "=r"(r[1]), "=r"(r[2]), "=r"(r[3]) : "r"(addr));
}
__device__ __forceinline__ void cp16(uint32_t dst, const void* src) {
    asm volatile("cp.async.cg.shared.global [%0], [%1], 16;" :: "r"(dst), "l"(src));
}
#define CP_COMMIT()  asm volatile("cp.async.commit_group;" ::: "memory")
#define CP_WAIT(n)   asm volatile("cp.async.wait_group %0;" :: "n"(n) : "memory")
#define SW(o)        ((o) ^ (((o) >> 3) & 0x70))

__device__ __forceinline__ float fexp(float x) {
    x = fmaxf(x, -80.f);
    float t  = x * 1.4426950408889634f;
    float fi = floorf(t);
    float f  = t - fi;
    float p  = 1.8775767e-3f;
    p = fmaf(p, f, 8.9893397e-3f);
    p = fmaf(p, f, 5.5826318e-2f);
    p = fmaf(p, f, 2.4015361e-1f);
    p = fmaf(p, f, 6.9315308e-1f);
    p = fmaf(p, f, 1.0f);
    return __int_as_float(__float_as_int(p) + (((int)fi) << 23));
}

// ---------------------------------------------------------------------------
// K0a: X fp32 -> fp16 convert
// ---------------------------------------------------------------------------
__global__ __launch_bounds__(256) void k0_cvtX(
    const float* __restrict__ src, int n4)
{
    int i = blockIdx.x * 256 + threadIdx.x;
    if (i >= n4) return;
    float4 v = reinterpret_cast<const float4*>(src)[i];
    ushort4 H;
    H.x = __half_as_ushort(__float2half_rn(v.x));
    H.y = __half_as_ushort(__float2half_rn(v.y));
    H.z = __half_as_ushort(__float2half_rn(v.z));
    H.w = __half_as_ushort(__float2half_rn(v.w));
    reinterpret_cast<ushort4*>(g_Xh)[i] = H;
}

// ---------------------------------------------------------------------------
// K0b: P + W1 + W2 fp32 -> fp16 convert in one launch
// ---------------------------------------------------------------------------
#define N4P (Cq * Dq / 4)
#define N4W (NHq * HIDq * HDq / 4)

__global__ __launch_bounds__(256) void k0_misc(
    const float* __restrict__ P, const float* __restrict__ W1,
    const float* __restrict__ W2)
{
    int i = blockIdx.x * 256 + threadIdx.x;
    const float* src;
    __half* dst;
    if (i < N4P)            { src = P;  dst = g_Ph; }
    else {
        i -= N4P;
        if (i < N4W)        { src = W1; dst = g_W1b; }
        else                { i -= N4W; if (i >= N4W) return; src = W2; dst = g_W2b; }
    }
    float4 v = reinterpret_cast<const float4*>(src)[i];
    ushort4 H;
    H.x = __half_as_ushort(__float2half_rn(v.x));
    H.y = __half_as_ushort(__float2half_rn(v.y));
    H.z = __half_as_ushort(__float2half_rn(v.z));
    H.w = __half_as_ushort(__float2half_rn(v.w));
    reinterpret_cast<ushort4*>(dst)[i] = H;
}

// ---------------------------------------------------------------------------
// KF: fused per-(head, 128-token tile) kernel — 96 KB smem, 2 CTAs/SM.
//   Phase A: Hi = X @ P_h^T + bP (fp16 HMMA, 12 K-chunks, 2-stage pipeline)
//   Phase B: logits via 4 hidden-chunks of 96, single-buffered W tiles
//   Phase C: masked softmax-pool partials, Hi read back as fp16.
// ---------------------------------------------------------------------------
#define OHH   0
#define OMK   26624
#define ORD   27136
#define OB    29440
#define ASTG  28672
#define OF    OB
#define OW1   (OB + 26624)
#define OW2   (OB + 46592)
#define KF_SMEM 96000
#define SHI   208

__global__ __launch_bounds__(256, 2) void kf_fused(
    const __half* __restrict__ Xh, const __half* __restrict__ Ph,
    const float* __restrict__ bP,
    const float* __restrict__ b1, const float* __restrict__ b2,
    const float* __restrict__ mask)
{
    extern __shared__ char smem[];
    const uint32_t sb = smem_u32(smem);
    const int tid = threadIdx.x, wid = tid >> 5, lane = tid & 31;
    const int head  = blockIdx.x;
    const int mt    = blockIdx.y;
    const int mtile = mt * 128;
    const int batch = mt >> 2;
    const int soff  = (mt & 3) * 128;
    const int wm  = (wid >> 1) * 32;
    const int wnA = (wid & 1) * 48;

    // ---- prefix-mask early exit (CTA-uniform branch) ----
    if (mask[batch * Sq + soff] < 0.5f) {
        if (tid < 96) {
            float* dst = &g_part[(size_t)mt * 3 * Cq + head * HDq + tid];
            dst[0]      = -1e30f;
            dst[Cq]     = 0.f;
            dst[2 * Cq] = 0.f;
        }
        return;
    }

    const __half* W1h = g_W1b + (size_t)head * HIDq * HDq;
    const __half* W2h = g_W2b + (size_t)head * HDq * HIDq;
    const float* b1h = b1 + head * HIDq;
    const float* b2h = b2 + head * HDq;

    // ======================= Phase A: projection GEMM ======================
    auto load_chunk = [&](int c, int s) {
        const int kb = c * 64;
        const uint32_t st = sb + OB + s * ASTG;
        #pragma unroll
        for (int t = 0; t < 4; t++) {              // X: 128 rows x 8 col16
            int idx = tid + t * 256;
            int row = idx >> 3, c16 = idx & 7;
            uint32_t off = SW(row * 128 + c16 * 16);
            cp16(st + off, Xh + (size_t)(mtile + row) * Dq + kb + c16 * 8);
        }
        #pragma unroll
        for (int t = 0; t < 3; t++) {              // P: 96 rows x 8 col16
            int idx = tid + t * 256;
            int row = idx >> 3, c16 = idx & 7;
            uint32_t off = SW(row * 128 + c16 * 16);
            cp16(st + 16384 + off, Ph + (size_t)(head * HDq + row) * Dq + kb + c16 * 8);
        }
        CP_COMMIT();
    };

    float accA[2][6][4];
    #pragma unroll
    for (int a = 0; a < 2; a++)
        #pragma unroll
        for (int b = 0; b < 6; b++)
            #pragma unroll
            for (int c = 0; c < 4; c++) accA[a][b][c] = 0.f;

    load_chunk(0, 0);
    #pragma unroll 1
    for (int c = 0; c < 12; c++) {
        if (c + 1 < 12) { load_chunk(c + 1, (c + 1) & 1); CP_WAIT(1); }
        else            { CP_WAIT(0); }
        __syncthreads();

        const uint32_t st  = sb + OB + (c & 1) * ASTG;
        const uint32_t sXh = st, sPh = st + 16384;
        #pragma unroll
        for (int ks = 0; ks < 4; ks++) {
            uint32_t ah[2][4], bh[3][4];
            #pragma unroll
            for (int mf = 0; mf < 2; mf++) {
                int row = wm + mf * 16 + (lane & 15);
                ldsm_x4(ah[mf], sXh + SW(row * 128 + ((lane >> 4) + ks * 2) * 16));
            }
            #pragma unroll
            for (int p = 0; p < 3; p++) {
                int g = lane >> 3;
                int row = wnA + p * 16 + (g >> 1) * 8 + (lane & 7);
                ldsm_x4(bh[p], sPh + SW(row * 128 + (ks * 2 + (g & 1)) * 16));
            }
            #pragma unroll
            for (int mf = 0; mf < 2; mf++)
                #pragma unroll
                for (int nf = 0; nf < 6; nf++)
                    mma16816(accA[mf][nf], ah[mf], &bh[nf >> 1][(nf & 1) * 2]);
        }
        __syncthreads();      // all MMAs on this stage done before overwrite
    }

    // Phase A epilogue: accA + bias -> Hi fp16 (OHH); stage mask
    float* mk = reinterpret_cast<float*>(smem + OMK);
    #pragma unroll
    for (int mf = 0; mf < 2; mf++) {
        const int m0 = wm + mf * 16 + (lane >> 2);
        #pragma unroll
        for (int nf = 0; nf < 6; nf++) {
            const int n = wnA + nf * 8 + 2 * (lane & 3);
            const float c0 = __ldg(&bP[head * HDq + n]);
            const float c1 = __ldg(&bP[head * HDq + n + 1]);
            __half2 p0 = __floats2half2_rn(accA[mf][nf][0] + c0, accA[mf][nf][1] + c1);
            __half2 p1 = __floats2half2_rn(accA[mf][nf][2] + c0, accA[mf][nf][3] + c1);
            *reinterpret_cast<uint32_t*>(smem + OHH + m0 * SHI + n * 2) =
                *reinterpret_cast<uint32_t*>(&p0);
            *reinterpret_cast<uint32_t*>(smem + OHH + (m0 + 8) * SHI + n * 2) =
                *reinterpret_cast<uint32_t*>(&p1);
        }
    }
    if (tid < 128) mk[tid] = mask[batch * Sq + soff + tid];

    // ========== Phase B: MLP, 4 hidden chunks of 96, single W buffer =======
    auto load_w = [&](int jc) {
        const int j0 = jc * 96;
        #pragma unroll
        for (int t = 0; t < 5; t++) {              // W1c: 96 x 96 = 1152 cells
            int idx = tid + t * 256;
            if (idx < 1152) {
                int row = idx / 12, c16 = idx % 12;
                cp16(sb + OW1 + row * SHI + c16 * 16,
                     W1h + (size_t)(j0 + row) * HDq + c16 * 8);
            }
        }
        #pragma unroll
        for (int t = 0; t < 5; t++) {              // W2c: 96 x 96 = 1152 cells
            int idx = tid + t * 256;
            if (idx < 1152) {
                int row = idx / 12, c16 = idx % 12;
                cp16(sb + OW2 + row * SHI + c16 * 16,
                     W2h + (size_t)row * HIDq + j0 + c16 * 8);
            }
        }
        CP_COMMIT();
    };

    float acc2[2][6][4];
    #pragma unroll
    for (int a = 0; a < 2; a++)
        #pragma unroll
        for (int b = 0; b < 6; b++)
            #pragma unroll
            for (int c = 0; c < 4; c++) acc2[a][b][c] = 0.f;

    #pragma unroll 1
    for (int jc = 0; jc < 4; jc++) {
        const int j0 = jc * 96;
        __syncthreads();            // prev chunk's W/F reads done; OHH visible (jc=0)
        load_w(jc);
        CP_WAIT(0);
        __syncthreads();            // W chunk visible

        float acc1[2][6][4];
        #pragma unroll
        for (int a = 0; a < 2; a++)
            #pragma unroll
            for (int b = 0; b < 6; b++)
                #pragma unroll
                for (int c = 0; c < 4; c++) acc1[a][b][c] = 0.f;

        // ---- layer 1: F = relu(Hi @ W1c^T + b1), K=96, N=96 ----
        #pragma unroll
        for (int ks = 0; ks < 6; ks++) {
            uint32_t afr[2][4], bfr[3][4];
            #pragma unroll
            for (int mf = 0; mf < 2; mf++) {
                int row = wm + mf * 16 + (lane & 15);
                ldsm_x4(afr[mf], sb + OHH + row * SHI + (lane >> 4) * 16 + ks * 32);
            }
            #pragma unroll
            for (int p = 0; p < 3; p++) {
                int g = lane >> 3;
                int row = wnA + p * 16 + (g >> 1) * 8 + (lane & 7);
                ldsm_x4(bfr[p], sb + OW1 + row * SHI + (g & 1) * 16 + ks * 32);
            }
            #pragma unroll
            for (int mf = 0; mf < 2; mf++)
                #pragma unroll
                for (int nf = 0; nf < 6; nf++)
                    mma16816(acc1[mf][nf], afr[mf], &bfr[nf >> 1][(nf & 1) * 2]);
        }

        // relu + b1 -> F (fp16)
        #pragma unroll
        for (int mf = 0; mf < 2; mf++) {
            const int m0 = wm + mf * 16 + (lane >> 2);
            #pragma unroll
            for (int nf = 0; nf < 6; nf++) {
                const int jl = wnA + nf * 8 + 2 * (lane & 3);
                const float c0 = __ldg(&b1h[j0 + jl]), c1 = __ldg(&b1h[j0 + jl + 1]);
                __half2 p0 = __floats2half2_rn(fmaxf(acc1[mf][nf][0] + c0, 0.f),
                                               fmaxf(acc1[mf][nf][1] + c1, 0.f));
                __half2 p1 = __floats2half2_rn(fmaxf(acc1[mf][nf][2] + c0, 0.f),
                                               fmaxf(acc1[mf][nf][3] + c1, 0.f));
                *reinterpret_cast<uint32_t*>(smem + OF + m0 * SHI + jl * 2) =
                    *reinterpret_cast<uint32_t*>(&p0);
                *reinterpret_cast<uint32_t*>(smem + OF + (m0 + 8) * SHI + jl * 2) =
                    *reinterpret_cast<uint32_t*>(&p1);
            }
        }
        __syncthreads();            // F visible

        // ---- layer 2 partial: acc2 += F @ W2c^T, K=96, N=96 ----
        #pragma unroll
        for (int ks = 0; ks < 6; ks++) {
            uint32_t afr[2][4], bfr[3][4];
            #pragma unroll
            for (int mf = 0; mf < 2; mf++) {
                int row = wm + mf * 16 + (lane & 15);
                ldsm_x4(afr[mf], sb + OF + row * SHI + (lane >> 4) * 16 + ks * 32);
            }
            #pragma unroll
            for (int p = 0; p < 3; p++) {
                int g = lane >> 3;
                int row = wnA + p * 16 + (g >> 1) * 8 + (lane & 7);
                ldsm_x4(bfr[p], sb + OW2 + row * SHI + (g & 1) * 16 + ks * 32);
            }
            #pragma unroll
            for (int mf = 0; mf < 2; mf++)
                #pragma unroll
                for (int nf = 0; nf < 6; nf++)
                    mma16816(acc2[mf][nf], afr[mf], &bfr[nf >> 1][(nf & 1) * 2]);
        }
    }

    // ===================== Phase C: softmax-pool partials ==================
    __syncthreads();                // last L2 MMAs done; OB region reusable
    float* Lg = reinterpret_cast<float*>(smem + OB);    // logits [128][97]
    #pragma unroll
    for (int mf = 0; mf < 2; mf++) {
        const int m0 = wm + mf * 16 + (lane >> 2);
        #pragma unroll
        for (int nf = 0; nf < 6; nf++) {
            const int n = wnA + nf * 8 + 2 * (lane & 3);
            const float c0 = __ldg(&b2h[n]), c1 = __ldg(&b2h[n + 1]);
            Lg[m0 * 97 + n]           = acc2[mf][nf][0] + c0;
            Lg[m0 * 97 + n + 1]       = acc2[mf][nf][1] + c1;
            Lg[(m0 + 8) * 97 + n]     = acc2[mf][nf][2] + c0;
            Lg[(m0 + 8) * 97 + n + 1] = acc2[mf][nf][3] + c1;
        }
    }
    __syncthreads();

    float* red = reinterpret_cast<float*>(smem + ORD);
    if (tid < 192) {
        const int ch = tid % 96, half = tid / 96;
        float m = -1e30f, l = 0.f, a = 0.f;
        for (int t = half * 64; t < half * 64 + 64; t++) {
            if (mk[t] > 0.5f) {
                float x  = Lg[t * 97 + ch];
                float hv = __half2float(*reinterpret_cast<const __half*>(
                               smem + OHH + t * SHI + ch * 2));
                float n  = fmaxf(m, x);
                float sc = fexp(m - n), w = fexp(x - n);
                l = fmaf(l, sc, w);
                a = fmaf(a, sc, w * hv);
                m = n;
            }
        }
        red[(half * 3 + 0) * 96 + ch] = m;
        red[(half * 3 + 1) * 96 + ch] = l;
        red[(half * 3 + 2) * 96 + ch] = a;
    }
    __syncthreads();
    if (tid < 96) {
        const int ch = tid;
        float m0 = red[0 * 96 + ch], l0 = red[1 * 96 + ch], a0 = red[2 * 96 + ch];
        float m1 = red[3 * 96 + ch], l1 = red[4 * 96 + ch], a1 = red[5 * 96 + ch];
        float n  = fmaxf(fmaxf(m0, m1), -1e30f);
        float s0 = fexp(m0 - n), s1 = fexp(m1 - n);
        float* dst = &g_part[(size_t)mt * 3 * Cq + head * HDq + ch];
        dst[0]      = n;
        dst[Cq]     = l0 * s0 + l1 * s1;
        dst[2 * Cq] = a0 * s0 + a1 * s1;
    }
}

// ---------------------------------------------------------------------------
// K3: merge 4 chunk partials per (batch, channel) -> output
// ---------------------------------------------------------------------------
__global__ __launch_bounds__(256) void k3_reduce(float* __restrict__ out)
{
    const int idx = blockIdx.x * 256 + threadIdx.x;
    const int b = idx / Cq, ch = idx % Cq;

    float m = -1e30f;
    #pragma unroll
    for (int c = 0; c < 4; c++)
        m = fmaxf(m, g_part[(size_t)(b * 4 + c) * 3 * Cq + ch]);

    float l = 0.f, a = 0.f;
    #pragma unroll
    for (int c = 0; c < 4; c++) {
        const float* p = &g_part[(size_t)(b * 4 + c) * 3 * Cq + ch];
        float s = fexp(p[0] - m);
        l = fmaf(p[Cq],     s, l);
        a = fmaf(p[2 * Cq], s, a);
    }
    out[idx] = a / l;
}

// ---------------------------------------------------------------------------
extern "C" void kernel_launch(void* const* d_in, const int* in_sizes, int n_in,
                              void* d_out, int out_size)
{
    const float* X    = (const float*)d_in[0];
    const float* mask = (const float*)d_in[1];
    const float* P    = (const float*)d_in[2];
    const float* bP   = (const float*)d_in[3];
    const float* W1   = (const float*)d_in[4];
    const float* b1   = (const float*)d_in[5];
    const float* W2   = (const float*)d_in[6];
    const float* b2   = (const float*)d_in[7];
    float* out = (float*)d_out;

    cudaFuncSetAttribute(kf_fused, cudaFuncAttributeMaxDynamicSharedMemorySize, KF_SMEM);

    __half *Xh, *Ph;
    cudaGetSymbolAddress((void**)&Xh, g_Xh);
    cudaGetSymbolAddress((void**)&Ph, g_Ph);

    // K0a: X convert to fp16
    {
        int n4x = Mq * Dq / 4;
        k0_cvtX<<<(n4x + 255) / 256, 256>>>(X, n4x);
    }
    // K0b: P + W converts in one launch
    {
        int ncells = N4P + 2 * N4W;
        k0_misc<<<(ncells + 255) / 256, 256>>>(P, W1, W2);
    }

    // KF: fused projection + MLP + partial softmax-pool (2 CTAs/SM)
    dim3 gf(NHq, Mq / 128);
    kf_fused<<<gf, 256, KF_SMEM>>>(Xh, Ph, bP, b1, b2, mask);

    // K3: merge partials
    k3_reduce<<<(Bq * Cq) / 256, 256>>>(out);
}